// round 1
// baseline (speedup 1.0000x reference)
#include <cuda_runtime.h>
#include <cstdint>

// Problem dims
#define NIMG 32
#define CCH 16
#define HH 224
#define WW 224
#define HWSZ (HH*WW)          // 50176
#define NPIX (NIMG*HWSZ)      // 1,605,632 pixels
#define TOTAL (NIMG*CCH*HWSZ) // 25,690,112 elements

// Conv tiling
#define TH 16
#define TW 32
#define GX (WW/TW)   // 7
#define GY (HH/TH)   // 14
#define NBLK (GX*GY*NIMG)  // 3136

// ---------------- scratch (device globals: no allocations allowed) ----------
__device__ unsigned g_maxbits;          // max|x| as float bits (all >= 0)
__device__ float    g_stepw;            // weight quant step
__device__ int4     g_wq[16*9];         // packed int8 weights [oc][tap], 4 ch per int
__device__ int4     g_xq[NPIX];         // packed int8 activations [n][h][w], 16 ch = int4
__device__ double   g_part[NBLK][32];   // per-block partial sums: [.. ][ch]=sumI, [16+ch]=sumI^2
__device__ float    g_scale[16];        // fused BN scale (includes s = stepx*stepw)
__device__ float    g_bias[16];         // fused BN bias

// ---------------- k_init: reset + weight max + weight quantize/pack ---------
__global__ void k_init(const float* __restrict__ w) {
    __shared__ float red[256];
    __shared__ float s_stepw;
    int t = threadIdx.x;
    if (t == 0) g_maxbits = 0u;
    float m = 0.f;
    for (int i = t; i < 16*16*9; i += 256) m = fmaxf(m, fabsf(w[i]));
    red[t] = m; __syncthreads();
    for (int s = 128; s; s >>= 1) {
        if (t < s) red[t] = fmaxf(red[t], red[t+s]);
        __syncthreads();
    }
    if (t == 0) {
        float sw = __fdiv_rn(red[0], 127.0f);
        g_stepw = sw; s_stepw = sw;
    }
    __syncthreads();
    float sw = s_stepw;
    if (t < 144) {                       // 16 oc * 9 taps
        int oc = t / 9, tap = t % 9;
        int vals[4];
        #pragma unroll
        for (int g = 0; g < 4; ++g) {
            int packed = 0;
            #pragma unroll
            for (int b = 0; b < 4; ++b) {
                int c = g*4 + b;
                float v = w[(oc*16 + c)*9 + tap];
                float q = rintf(__fdiv_rn(v, sw));
                q = fminf(fmaxf(q, -127.f), 127.f);
                int qi = (int)q;
                packed |= (qi & 0xFF) << (8*b);
            }
            vals[g] = packed;
        }
        g_wq[oc*9 + tap] = make_int4(vals[0], vals[1], vals[2], vals[3]);
    }
}

// ---------------- k_xmax: global max|x| ------------------------------------
__global__ void k_xmax(const float4* __restrict__ x) {
    float m = 0.f;
    int stride = gridDim.x * blockDim.x;
    for (int i = blockIdx.x*blockDim.x + threadIdx.x; i < TOTAL/4; i += stride) {
        float4 v = x[i];
        m = fmaxf(m, fmaxf(fmaxf(fabsf(v.x), fabsf(v.y)), fmaxf(fabsf(v.z), fabsf(v.w))));
    }
    #pragma unroll
    for (int off = 16; off; off >>= 1)
        m = fmaxf(m, __shfl_xor_sync(0xFFFFFFFFu, m, off));
    __shared__ float red[8];
    int lane = threadIdx.x & 31, wp = threadIdx.x >> 5;
    if (lane == 0) red[wp] = m;
    __syncthreads();
    if (threadIdx.x == 0) {
        float mm = red[0];
        #pragma unroll
        for (int i = 1; i < 8; ++i) mm = fmaxf(mm, red[i]);
        atomicMax(&g_maxbits, __float_as_uint(mm));
    }
}

// ---------------- k_xq: quantize x -> packed int8 per pixel ----------------
__global__ void k_xq(const float* __restrict__ x) {
    int p = blockIdx.x*blockDim.x + threadIdx.x;
    if (p >= NPIX) return;
    float sx = __fdiv_rn(__uint_as_float(g_maxbits), 127.0f);
    int n = p / HWSZ;
    int rem = p - n*HWSZ;
    const float* base = x + (size_t)n*(CCH*HWSZ) + rem;
    int vals[4];
    #pragma unroll
    for (int g = 0; g < 4; ++g) {
        int packed = 0;
        #pragma unroll
        for (int b = 0; b < 4; ++b) {
            int c = g*4 + b;
            float v = base[(size_t)c*HWSZ];
            float q = rintf(__fdiv_rn(v, sx));
            q = fminf(fmaxf(q, -127.f), 127.f);
            int qi = (int)q;
            packed |= (qi & 0xFF) << (8*b);
        }
        vals[g] = packed;
    }
    g_xq[p] = make_int4(vals[0], vals[1], vals[2], vals[3]);
}

// ---------------- conv: dp4a, shared by stats and write passes --------------
template<bool WRITE>
__global__ void __launch_bounds__(256, 2) k_conv(float* __restrict__ out) {
    __shared__ int4 s_x[TH+2][TW+2];   // 18 x 34 int4 = 9792 B
    __shared__ int4 s_w[144];          // 2304 B
    __shared__ int    s_sumI[8][16];
    __shared__ double s_sumQ[8][16];

    int t = threadIdx.x;
    int n = blockIdx.z;
    int h0 = blockIdx.y * TH, w0 = blockIdx.x * TW;

    // load halo tile (zero padded)
    for (int i = t; i < (TH+2)*(TW+2); i += 256) {
        int r = i / (TW+2), cc = i - r*(TW+2);
        int gh = h0 - 1 + r, gw = w0 - 1 + cc;
        int4 v = make_int4(0,0,0,0);
        if ((unsigned)gh < (unsigned)HH && (unsigned)gw < (unsigned)WW)
            v = g_xq[n*HWSZ + gh*WW + gw];
        s_x[r][cc] = v;
    }
    if (t < 144) s_w[t] = g_wq[t];
    __syncthreads();

    int ty = t >> 5, tx = t & 31;      // 8 rows x 32 cols; 2 pixels per thread (rows ty, ty+8)
    int acc0[16], acc1[16];
    #pragma unroll
    for (int oc = 0; oc < 16; ++oc) { acc0[oc] = 0; acc1[oc] = 0; }

    #pragma unroll
    for (int ky = 0; ky < 3; ++ky) {
        #pragma unroll
        for (int kx = 0; kx < 3; ++kx) {
            int4 a0 = s_x[ty + ky][tx + kx];
            int4 a1 = s_x[ty + 8 + ky][tx + kx];
            int tap = ky*3 + kx;
            #pragma unroll
            for (int oc = 0; oc < 16; ++oc) {
                int4 wv = s_w[oc*9 + tap];
                int r0 = acc0[oc], r1 = acc1[oc];
                r0 = __dp4a(a0.x, wv.x, r0);
                r0 = __dp4a(a0.y, wv.y, r0);
                r0 = __dp4a(a0.z, wv.z, r0);
                r0 = __dp4a(a0.w, wv.w, r0);
                r1 = __dp4a(a1.x, wv.x, r1);
                r1 = __dp4a(a1.y, wv.y, r1);
                r1 = __dp4a(a1.z, wv.z, r1);
                r1 = __dp4a(a1.w, wv.w, r1);
                acc0[oc] = r0; acc1[oc] = r1;
            }
        }
    }

    if (WRITE) {
        int h = h0 + ty, wcol = w0 + tx;
        size_t ob = (size_t)n*CCH*HWSZ + (size_t)h*WW + wcol;
        #pragma unroll
        for (int oc = 0; oc < 16; ++oc) {
            float sc = g_scale[oc], bi = g_bias[oc];
            float y0 = fminf(fmaxf(fmaf((float)acc0[oc], sc, bi), 0.f), 6.f);
            float y1 = fminf(fmaxf(fmaf((float)acc1[oc], sc, bi), 0.f), 6.f);
            out[ob + (size_t)oc*HWSZ]            = y0;
            out[ob + (size_t)oc*HWSZ + 8*WW]     = y1;
        }
    } else {
        // exact per-channel integer stats
        #pragma unroll
        for (int oc = 0; oc < 16; ++oc) {
            int si = acc0[oc] + acc1[oc];
            double sq = (double)acc0[oc]*(double)acc0[oc]
                      + (double)acc1[oc]*(double)acc1[oc];
            #pragma unroll
            for (int off = 16; off; off >>= 1) {
                si += __shfl_down_sync(0xFFFFFFFFu, si, off);
                sq += __shfl_down_sync(0xFFFFFFFFu, sq, off);
            }
            if ((t & 31) == 0) { s_sumI[ty][oc] = si; s_sumQ[ty][oc] = sq; }
        }
        __syncthreads();
        if (t < 16) {
            double ts = 0.0, tq = 0.0;
            #pragma unroll
            for (int wp = 0; wp < 8; ++wp) { ts += (double)s_sumI[wp][t]; tq += s_sumQ[wp][t]; }
            int bf = (n*gridDim.y + blockIdx.y)*gridDim.x + blockIdx.x;
            g_part[bf][t]      = ts;
            g_part[bf][16 + t] = tq;
        }
    }
}

// ---------------- k_fin: reduce partials, compute BN affine -----------------
__global__ void k_fin(const float* __restrict__ gamma, const float* __restrict__ beta) {
    int t = threadIdx.x;              // 1024 threads = 32 warps, one per quantity
    int q = t >> 5, lane = t & 31;
    double s = 0.0;
    for (int b = lane; b < NBLK; b += 32) s += g_part[b][q];
    #pragma unroll
    for (int off = 16; off; off >>= 1) s += __shfl_down_sync(0xFFFFFFFFu, s, off);
    __shared__ double tot[32];
    if (lane == 0) tot[q] = s;
    __syncthreads();
    if (t < 16) {
        double stepx = (double)__fdiv_rn(__uint_as_float(g_maxbits), 127.0f);
        double sc = stepx * (double)g_stepw;      // y = sc * acc (exact)
        double M = (double)NPIX;
        double mean = sc * tot[t] / M;
        double ey2  = sc * sc * tot[16 + t] / M;
        double var  = ey2 - mean*mean;
        double inv  = (double)gamma[t] / sqrt(var + 1e-5);
        g_scale[t] = (float)(sc * inv);
        g_bias[t]  = (float)((double)beta[t] - mean * inv);
    }
}

// ---------------- launch ----------------------------------------------------
extern "C" void kernel_launch(void* const* d_in, const int* in_sizes, int n_in,
                              void* d_out, int out_size) {
    const float* x     = (const float*)d_in[0];
    const float* wgt   = (const float*)d_in[1];
    const float* gamma = (const float*)d_in[2];
    const float* beta  = (const float*)d_in[3];
    float* out = (float*)d_out;

    k_init<<<1, 256>>>(wgt);
    k_xmax<<<1184, 256>>>((const float4*)x);
    k_xq<<<(NPIX + 255)/256, 256>>>(x);
    dim3 g(GX, GY, NIMG);
    k_conv<false><<<g, 256>>>(nullptr);
    k_fin<<<1, 1024>>>(gamma, beta);
    k_conv<true><<<g, 256>>>(out);
}

// round 2
// speedup vs baseline: 1.4843x; 1.4843x over previous
#include <cuda_runtime.h>
#include <cstdint>

// Problem dims
#define NIMG 32
#define CCH 16
#define HH 224
#define WW 224
#define HWSZ (HH*WW)          // 50176
#define NPIX (NIMG*HWSZ)      // 1,605,632 pixels
#define TOTAL (NIMG*CCH*HWSZ) // 25,690,112 elements

// Conv tiling: 16x16 pixel tile, 256 threads, 2 warp-groups of 8 oc each
#define TH 16
#define TW 16
#define GX (WW/TW)   // 14
#define GY (HH/TH)   // 14
#define NBLK (GX*GY*NIMG)  // 6272

// ---------------- scratch (device globals: no allocations allowed) ----------
__device__ unsigned  g_maxbits;          // max|x| as float bits (all >= 0)
__device__ float     g_stepw;            // weight quant step
__device__ int4      g_wq[16*9];         // packed int8 weights [oc][tap], 16 ch
__device__ int4      g_xq[NPIX];         // packed int8 activations [n][h][w]
__device__ long long g_partI[NBLK][16];  // per-block per-oc sum of acc
__device__ long long g_partQ[NBLK][16];  // per-block per-oc sum of acc^2
__device__ float     g_scale[16];        // fused BN scale (includes stepx*stepw)
__device__ float     g_bias[16];         // fused BN bias

// ---------------- k_init: reset + weight max + weight quantize/pack ---------
__global__ void k_init(const float* __restrict__ w) {
    __shared__ float red[256];
    __shared__ float s_stepw;
    int t = threadIdx.x;
    if (t == 0) g_maxbits = 0u;
    float m = 0.f;
    for (int i = t; i < 16*16*9; i += 256) m = fmaxf(m, fabsf(w[i]));
    red[t] = m; __syncthreads();
    for (int s = 128; s; s >>= 1) {
        if (t < s) red[t] = fmaxf(red[t], red[t+s]);
        __syncthreads();
    }
    if (t == 0) {
        float sw = __fdiv_rn(red[0], 127.0f);
        g_stepw = sw; s_stepw = sw;
    }
    __syncthreads();
    float sw = s_stepw;
    if (t < 144) {                       // 16 oc * 9 taps
        int oc = t / 9, tap = t % 9;
        int vals[4];
        #pragma unroll
        for (int g = 0; g < 4; ++g) {
            int packed = 0;
            #pragma unroll
            for (int b = 0; b < 4; ++b) {
                int c = g*4 + b;
                float v = w[(oc*16 + c)*9 + tap];
                float q = rintf(__fdiv_rn(v, sw));
                q = fminf(fmaxf(q, -127.f), 127.f);
                int qi = (int)q;
                packed |= (qi & 0xFF) << (8*b);
            }
            vals[g] = packed;
        }
        g_wq[oc*9 + tap] = make_int4(vals[0], vals[1], vals[2], vals[3]);
    }
}

// ---------------- k_xmax: global max|x| ------------------------------------
__global__ void k_xmax(const float4* __restrict__ x) {
    float m = 0.f;
    int stride = gridDim.x * blockDim.x;
    for (int i = blockIdx.x*blockDim.x + threadIdx.x; i < TOTAL/4; i += stride) {
        float4 v = x[i];
        m = fmaxf(m, fmaxf(fmaxf(fabsf(v.x), fabsf(v.y)), fmaxf(fabsf(v.z), fabsf(v.w))));
    }
    #pragma unroll
    for (int off = 16; off; off >>= 1)
        m = fmaxf(m, __shfl_xor_sync(0xFFFFFFFFu, m, off));
    __shared__ float red[8];
    int lane = threadIdx.x & 31, wp = threadIdx.x >> 5;
    if (lane == 0) red[wp] = m;
    __syncthreads();
    if (threadIdx.x == 0) {
        float mm = red[0];
        #pragma unroll
        for (int i = 1; i < 8; ++i) mm = fmaxf(mm, red[i]);
        atomicMax(&g_maxbits, __float_as_uint(mm));
    }
}

// ---------------- k_xq: quantize x -> packed int8, 4 pixels per thread ------
__global__ void k_xq(const float* __restrict__ x) {
    int p4 = blockIdx.x*blockDim.x + threadIdx.x;
    if (p4 >= NPIX/4) return;
    float sx = __fdiv_rn(__uint_as_float(g_maxbits), 127.0f);
    int n = p4 / (HWSZ/4);
    int rem4 = p4 - n*(HWSZ/4);
    const float* base = x + (size_t)n*(CCH*HWSZ) + rem4*4;
    int out[4][4];   // [pixel][channel-group]
    #pragma unroll
    for (int c = 0; c < 16; ++c) {
        float4 v = *(const float4*)(base + (size_t)c*HWSZ);
        float f[4] = {v.x, v.y, v.z, v.w};
        int g = c >> 2, b = c & 3;
        #pragma unroll
        for (int px = 0; px < 4; ++px) {
            float q = rintf(__fdiv_rn(f[px], sx));
            q = fminf(fmaxf(q, -127.f), 127.f);
            int qi = (int)q;
            if (b == 0) out[px][g] = (qi & 0xFF);
            else out[px][g] |= (qi & 0xFF) << (8*b);
        }
    }
    int pix = n*HWSZ + rem4*4;
    #pragma unroll
    for (int px = 0; px < 4; ++px)
        g_xq[pix + px] = make_int4(out[px][0], out[px][1], out[px][2], out[px][3]);
}

// ---------------- conv: dp4a, 8 oc x 2 pixels per thread --------------------
template<bool WRITE>
__global__ void __launch_bounds__(256, 4) k_conv(float* __restrict__ out) {
    __shared__ int4 s_x[TH+2][TW+2];    // 18 x 18 int4 = 5184 B
    __shared__ int4 s_w[144];           // 2304 B
    __shared__ long long s_I[8][8];
    __shared__ long long s_Q[8][8];

    int t = threadIdx.x;
    int n = blockIdx.z;
    int h0 = blockIdx.y * TH, w0 = blockIdx.x * TW;

    // load halo tile (zero padded)
    for (int i = t; i < 18*18; i += 256) {
        int r = i / 18, cc = i - r*18;
        int gh = h0 - 1 + r, gw = w0 - 1 + cc;
        int4 v = make_int4(0,0,0,0);
        if ((unsigned)gh < (unsigned)HH && (unsigned)gw < (unsigned)WW)
            v = g_xq[n*HWSZ + gh*WW + gw];
        s_x[r][cc] = v;
    }
    if (t < 144) s_w[t] = g_wq[t];
    __syncthreads();

    int ocbase = (t >> 7) * 8;          // warp-group 0: oc 0-7, group 1: oc 8-15
    int wt = t & 127;
    int r = wt >> 4, c = wt & 15;       // pixel rows r and r+8, col c

    int acc0[8], acc1[8];
    #pragma unroll
    for (int j = 0; j < 8; ++j) { acc0[j] = 0; acc1[j] = 0; }

    #pragma unroll
    for (int ky = 0; ky < 3; ++ky) {
        #pragma unroll
        for (int kx = 0; kx < 3; ++kx) {
            int4 a0 = s_x[r + ky][c + kx];
            int4 a1 = s_x[r + 8 + ky][c + kx];
            int tap = ky*3 + kx;
            #pragma unroll
            for (int j = 0; j < 8; ++j) {
                int4 wv = s_w[(ocbase + j)*9 + tap];
                int r0 = acc0[j], r1 = acc1[j];
                r0 = __dp4a(a0.x, wv.x, r0);
                r0 = __dp4a(a0.y, wv.y, r0);
                r0 = __dp4a(a0.z, wv.z, r0);
                r0 = __dp4a(a0.w, wv.w, r0);
                r1 = __dp4a(a1.x, wv.x, r1);
                r1 = __dp4a(a1.y, wv.y, r1);
                r1 = __dp4a(a1.z, wv.z, r1);
                r1 = __dp4a(a1.w, wv.w, r1);
                acc0[j] = r0; acc1[j] = r1;
            }
        }
    }

    if (WRITE) {
        int h = h0 + r, wcol = w0 + c;
        size_t ob = (size_t)n*CCH*HWSZ + (size_t)h*WW + wcol;
        #pragma unroll
        for (int j = 0; j < 8; ++j) {
            int oc = ocbase + j;
            float sc = g_scale[oc], bi = g_bias[oc];
            float y0 = fminf(fmaxf(fmaf((float)acc0[j], sc, bi), 0.f), 6.f);
            float y1 = fminf(fmaxf(fmaf((float)acc1[j], sc, bi), 0.f), 6.f);
            out[ob + (size_t)oc*HWSZ]        = y0;
            out[ob + (size_t)oc*HWSZ + 8*WW] = y1;
        }
    } else {
        // exact per-channel integer stats: int32 REDUX + int64 shfl reduce
        int warp = t >> 5, lane = t & 31;
        #pragma unroll
        for (int j = 0; j < 8; ++j) {
            int si = __reduce_add_sync(0xFFFFFFFFu, acc0[j] + acc1[j]);
            long long sq = (long long)acc0[j]*(long long)acc0[j]
                         + (long long)acc1[j]*(long long)acc1[j];
            #pragma unroll
            for (int off = 16; off; off >>= 1)
                sq += __shfl_down_sync(0xFFFFFFFFu, sq, off);
            if (lane == 0) { s_I[warp][j] = (long long)si; s_Q[warp][j] = sq; }
        }
        __syncthreads();
        if (t < 16) {
            int grp = t >> 3, ocw = t & 7;   // warps grp*4..grp*4+3 hold oc t
            long long ti = 0, tq = 0;
            #pragma unroll
            for (int wp = 0; wp < 4; ++wp) {
                ti += s_I[grp*4 + wp][ocw];
                tq += s_Q[grp*4 + wp][ocw];
            }
            int bf = (n*gridDim.y + blockIdx.y)*gridDim.x + blockIdx.x;
            g_partI[bf][t] = ti;
            g_partQ[bf][t] = tq;
        }
    }
}

// ---------------- k_fin: reduce partials, compute BN affine -----------------
__global__ void k_fin(const float* __restrict__ gamma, const float* __restrict__ beta) {
    int t = threadIdx.x;              // 1024 threads = 32 warps, one per quantity
    int q = t >> 5, lane = t & 31;
    double s = 0.0;
    if (q < 16) {
        for (int b = lane; b < NBLK; b += 32) s += (double)g_partI[b][q];
    } else {
        int qq = q - 16;
        for (int b = lane; b < NBLK; b += 32) s += (double)g_partQ[b][qq];
    }
    #pragma unroll
    for (int off = 16; off; off >>= 1) s += __shfl_down_sync(0xFFFFFFFFu, s, off);
    __shared__ double tot[32];
    if (lane == 0) tot[q] = s;
    __syncthreads();
    if (t < 16) {
        double stepx = (double)__fdiv_rn(__uint_as_float(g_maxbits), 127.0f);
        double sc = stepx * (double)g_stepw;      // y = sc * acc (exact)
        double M = (double)NPIX;
        double mean = sc * tot[t] / M;
        double ey2  = sc * sc * tot[16 + t] / M;
        double var  = ey2 - mean*mean;
        double inv  = (double)gamma[t] / sqrt(var + 1e-5);
        g_scale[t] = (float)(sc * inv);
        g_bias[t]  = (float)((double)beta[t] - mean * inv);
    }
}

// ---------------- launch ----------------------------------------------------
extern "C" void kernel_launch(void* const* d_in, const int* in_sizes, int n_in,
                              void* d_out, int out_size) {
    const float* x     = (const float*)d_in[0];
    const float* wgt   = (const float*)d_in[1];
    const float* gamma = (const float*)d_in[2];
    const float* beta  = (const float*)d_in[3];
    float* out = (float*)d_out;

    k_init<<<1, 256>>>(wgt);
    k_xmax<<<1184, 256>>>((const float4*)x);
    k_xq<<<(NPIX/4 + 255)/256, 256>>>(x);
    dim3 g(GX, GY, NIMG);
    k_conv<false><<<g, 256>>>(nullptr);
    k_fin<<<1, 1024>>>(gamma, beta);
    k_conv<true><<<g, 256>>>(out);
}